// round 1
// baseline (speedup 1.0000x reference)
#include <cuda_runtime.h>

// IMU preintegration (RmiModel): per batch, sequential scan over T-1 steps of
//   DCa = DC @ a_k
//   DR += DV*dt + 0.5*DCa*dt^2
//   DV += DCa*dt
//   DC  = DC @ so3_exp(w_k*dt)
// Parallelized via associative segment composition: segment = (Q, p, q, tau),
//   Q = Q1@Q2 ; p = p1 + Q1@p2 ; q = q1 + tau2*p1 + Q1@q2 ; tau = tau1 + tau2.
// One warp per batch; each lane runs a contiguous 32-step segment from identity
// (its local (DC,DV,DR,sum_dt) IS the segment transform), then a 5-round
// doubling-offset shuffle reduction combines segments in order.

__device__ __forceinline__ void so3_AB(float t2, float& A, float& Bc) {
    if (t2 > 0.25f) {               // exact fallback (never taken on this data)
        float th = sqrtf(t2);
        A  = sinf(th) / th;
        Bc = (1.0f - cosf(th)) / t2;
    } else {                        // Taylor, |err| < 1e-8 for t2 <= 0.25
        A  = 1.0f + t2 * (-1.0f/6.0f  + t2 * (1.0f/120.0f + t2 * (-1.0f/5040.0f)));
        Bc = 0.5f + t2 * (-1.0f/24.0f + t2 * (1.0f/720.0f + t2 * (-1.0f/40320.0f)));
    }
}

__global__ __launch_bounds__(256, 2)
void rmi_kernel(const float* __restrict__ x, float* __restrict__ out,
                int B, int T, int spl)
{
    const int gwarp = (blockIdx.x * blockDim.x + threadIdx.x) >> 5;
    const int lane  = threadIdx.x & 31;
    if (gwarp >= B) return;
    const int b = gwarp;
    const int nsteps = T - 1;

    const size_t base = (size_t)b * 7 * (size_t)T;
    const float* tt = x + base;
    const float* w0 = x + base + 1 * (size_t)T;
    const float* w1 = x + base + 2 * (size_t)T;
    const float* w2 = x + base + 3 * (size_t)T;
    const float* a0 = x + base + 4 * (size_t)T;
    const float* a1 = x + base + 5 * (size_t)T;
    const float* a2 = x + base + 6 * (size_t)T;

    // Local segment state: Q (row-major rotation), p (DV), r (DR), tau
    float Q[9] = {1.f,0.f,0.f, 0.f,1.f,0.f, 0.f,0.f,1.f};
    float p[3] = {0.f,0.f,0.f};
    float r[3] = {0.f,0.f,0.f};
    float tau  = 0.f;

    const int k0 = lane * spl;

    for (int k = k0; k < k0 + spl; k += 4) {
        float4 vt, vw0, vw1, vw2, va0, va1, va2;
        float tnext;
        if (k + 4 < T) {
            vt  = *reinterpret_cast<const float4*>(tt + k);
            tnext = tt[k + 4];
            vw0 = *reinterpret_cast<const float4*>(w0 + k);
            vw1 = *reinterpret_cast<const float4*>(w1 + k);
            vw2 = *reinterpret_cast<const float4*>(w2 + k);
            va0 = *reinterpret_cast<const float4*>(a0 + k);
            va1 = *reinterpret_cast<const float4*>(a1 + k);
            va2 = *reinterpret_cast<const float4*>(a2 + k);
        } else {
            // guarded tail (only last group of last lane, or odd shapes)
            float tv[4], w0v[4], w1v[4], w2v[4], a0v[4], a1v[4], a2v[4];
            #pragma unroll
            for (int j = 0; j < 4; j++) {
                bool ok = (k + j) < T;
                tv[j]  = ok ? tt[k + j] : 0.f;
                w0v[j] = ok ? w0[k + j] : 0.f;
                w1v[j] = ok ? w1[k + j] : 0.f;
                w2v[j] = ok ? w2[k + j] : 0.f;
                a0v[j] = ok ? a0[k + j] : 0.f;
                a1v[j] = ok ? a1[k + j] : 0.f;
                a2v[j] = ok ? a2[k + j] : 0.f;
            }
            vt  = make_float4(tv[0],  tv[1],  tv[2],  tv[3]);
            vw0 = make_float4(w0v[0], w0v[1], w0v[2], w0v[3]);
            vw1 = make_float4(w1v[0], w1v[1], w1v[2], w1v[3]);
            vw2 = make_float4(w2v[0], w2v[1], w2v[2], w2v[3]);
            va0 = make_float4(a0v[0], a0v[1], a0v[2], a0v[3]);
            va1 = make_float4(a1v[0], a1v[1], a1v[2], a1v[3]);
            va2 = make_float4(a2v[0], a2v[1], a2v[2], a2v[3]);
            tnext = (k + 4 < T) ? tt[k + 4] : 0.f;
        }

        float dts[4] = { vt.y - vt.x, vt.z - vt.y, vt.w - vt.z, tnext - vt.w };
        float wxs[4] = { vw0.x, vw0.y, vw0.z, vw0.w };
        float wys[4] = { vw1.x, vw1.y, vw1.z, vw1.w };
        float wzs[4] = { vw2.x, vw2.y, vw2.z, vw2.w };
        float axs[4] = { va0.x, va0.y, va0.z, va0.w };
        float ays[4] = { va1.x, va1.y, va1.z, va1.w };
        float azs[4] = { va2.x, va2.y, va2.z, va2.w };

        #pragma unroll
        for (int j = 0; j < 4; j++) {
            // dt = 0 makes this step exactly the identity transform
            float dt = ((k + j) < nsteps) ? dts[j] : 0.f;

            float ax = axs[j], ay = ays[j], az = azs[j];
            // DCa with current Q (pre-update DC)
            float ca0 = Q[0]*ax + Q[1]*ay + Q[2]*az;
            float ca1 = Q[3]*ax + Q[4]*ay + Q[5]*az;
            float ca2 = Q[6]*ax + Q[7]*ay + Q[8]*az;
            float hdt2 = 0.5f * dt * dt;
            r[0] += p[0]*dt + ca0*hdt2;
            r[1] += p[1]*dt + ca1*hdt2;
            r[2] += p[2]*dt + ca2*hdt2;
            p[0] += ca0*dt;
            p[1] += ca1*dt;
            p[2] += ca2*dt;
            tau  += dt;

            // R = so3_exp(w*dt) = I + A*K + B*(phi phi^T - t2 I)
            float px = wxs[j]*dt, py = wys[j]*dt, pz = wzs[j]*dt;
            float t2 = px*px + py*py + pz*pz;
            float A, Bc;
            so3_AB(t2, A, Bc);
            float Bxy = Bc*px*py, Bxz = Bc*px*pz, Byz = Bc*py*pz;
            float R00 = 1.0f + Bc*(px*px - t2);
            float R11 = 1.0f + Bc*(py*py - t2);
            float R22 = 1.0f + Bc*(pz*pz - t2);
            float R01 = Bxy - A*pz;
            float R10 = Bxy + A*pz;
            float R02 = Bxz + A*py;
            float R20 = Bxz - A*py;
            float R12 = Byz - A*px;
            float R21 = Byz + A*px;

            // Q = Q @ R
            float n0 = Q[0]*R00 + Q[1]*R10 + Q[2]*R20;
            float n1 = Q[0]*R01 + Q[1]*R11 + Q[2]*R21;
            float n2 = Q[0]*R02 + Q[1]*R12 + Q[2]*R22;
            float n3 = Q[3]*R00 + Q[4]*R10 + Q[5]*R20;
            float n4 = Q[3]*R01 + Q[4]*R11 + Q[5]*R21;
            float n5 = Q[3]*R02 + Q[4]*R12 + Q[5]*R22;
            float n6 = Q[6]*R00 + Q[7]*R10 + Q[8]*R20;
            float n7 = Q[6]*R01 + Q[7]*R11 + Q[8]*R21;
            float n8 = Q[6]*R02 + Q[7]*R12 + Q[8]*R22;
            Q[0]=n0; Q[1]=n1; Q[2]=n2;
            Q[3]=n3; Q[4]=n4; Q[5]=n5;
            Q[6]=n6; Q[7]=n7; Q[8]=n8;
        }
    }

    // Warp reduction: non-commutative segment composition, doubling offsets.
    // lane l combines its [l .. l+off-1] block with lane (l+off)'s block.
    #pragma unroll
    for (int off = 1; off < 32; off <<= 1) {
        float Q2[9], p2[3], r2[3], tau2;
        #pragma unroll
        for (int i = 0; i < 9; i++) Q2[i] = __shfl_down_sync(0xffffffffu, Q[i], off);
        #pragma unroll
        for (int i = 0; i < 3; i++) p2[i] = __shfl_down_sync(0xffffffffu, p[i], off);
        #pragma unroll
        for (int i = 0; i < 3; i++) r2[i] = __shfl_down_sync(0xffffffffu, r[i], off);
        tau2 = __shfl_down_sync(0xffffffffu, tau, off);

        float nQ[9];
        #pragma unroll
        for (int i = 0; i < 3; i++) {
            #pragma unroll
            for (int jj = 0; jj < 3; jj++) {
                nQ[3*i+jj] = Q[3*i+0]*Q2[0+jj] + Q[3*i+1]*Q2[3+jj] + Q[3*i+2]*Q2[6+jj];
            }
        }
        float np[3], nr[3];
        #pragma unroll
        for (int i = 0; i < 3; i++) {
            float Qp = Q[3*i+0]*p2[0] + Q[3*i+1]*p2[1] + Q[3*i+2]*p2[2];
            float Qr = Q[3*i+0]*r2[0] + Q[3*i+1]*r2[1] + Q[3*i+2]*r2[2];
            np[i] = p[i] + Qp;
            nr[i] = r[i] + tau2 * p[i] + Qr;
        }
        #pragma unroll
        for (int i = 0; i < 9; i++) Q[i] = nQ[i];
        #pragma unroll
        for (int i = 0; i < 3; i++) { p[i] = np[i]; r[i] = nr[i]; }
        tau += tau2;
    }

    if (lane == 0) {
        float* o = out + (size_t)b * 15;
        #pragma unroll
        for (int i = 0; i < 9; i++) o[i] = Q[i];
        o[9]  = p[0]; o[10] = p[1]; o[11] = p[2];
        o[12] = r[0]; o[13] = r[1]; o[14] = r[2];
    }
}

extern "C" void kernel_launch(void* const* d_in, const int* in_sizes, int n_in,
                              void* d_out, int out_size) {
    const float* x = (const float*)d_in[0];
    float* out = (float*)d_out;

    int B = out_size / 15;
    int T = in_sizes[0] / (7 * B);

    // steps-per-lane: cover T-1 steps across 32 lanes, multiple of 4 for float4 groups
    int spl = ((T - 1) + 31) / 32;
    spl = (spl + 3) & ~3;

    const int THREADS = 256;                 // 8 warps = 8 batches per block
    int total_warps = B;
    int blocks = (total_warps * 32 + THREADS - 1) / THREADS;
    rmi_kernel<<<blocks, THREADS>>>(x, out, B, T, spl);
}

// round 2
// speedup vs baseline: 1.2306x; 1.2306x over previous
#include <cuda_runtime.h>

// IMU preintegration (RmiModel). Associative segment composition:
//   segment = (Q, p, q, tau);  compose: Q=Q1Q2, p=p1+Q1 p2, q=q1+tau2 p1+Q1 q2, tau=tau1+tau2.
// One warp per batch. To keep global loads coalesced (lane stride 32B instead of
// 128B), each lane integrates only 8 contiguous steps per ROUND; a round covers
// 256 steps. After each round, a 5-stage shfl_down tree composes the 32 lane
// segments (result valid on lane 0), which is folded into a running total.

__device__ __forceinline__ void so3_AB(float t2, float& A, float& Bc) {
    if (t2 > 0.25f) {               // exact fallback (never taken on this data)
        float th = sqrtf(t2);
        A  = sinf(th) / th;
        Bc = (1.0f - cosf(th)) / t2;
    } else {                        // Taylor, |err| < 1e-8 for t2 <= 0.25
        A  = 1.0f + t2 * (-1.0f/6.0f  + t2 * (1.0f/120.0f + t2 * (-1.0f/5040.0f)));
        Bc = 0.5f + t2 * (-1.0f/24.0f + t2 * (1.0f/720.0f + t2 * (-1.0f/40320.0f)));
    }
}

__global__ __launch_bounds__(128, 4)
void rmi_kernel(const float* __restrict__ x, float* __restrict__ out,
                int B, int T)
{
    const int gwarp = (blockIdx.x * blockDim.x + threadIdx.x) >> 5;
    const int lane  = threadIdx.x & 31;
    if (gwarp >= B) return;
    const int b = gwarp;
    const int nsteps = T - 1;

    const size_t base = (size_t)b * 7 * (size_t)T;
    const float* tt = x + base;
    const float* w0 = x + base + 1 * (size_t)T;
    const float* w1 = x + base + 2 * (size_t)T;
    const float* w2 = x + base + 3 * (size_t)T;
    const float* a0 = x + base + 4 * (size_t)T;
    const float* a1 = x + base + 5 * (size_t)T;
    const float* a2 = x + base + 6 * (size_t)T;

    // Running total (valid on lane 0 only)
    float TQ[9], Tp[3], Tr[3], Ttau;

    const int rounds = (nsteps + 255) / 256;   // 256 steps per round (32 lanes x 8)

    for (int rr = 0; rr < rounds; rr++) {
        const int rbase = rr * 256;
        const int k = rbase + lane * 8;

        // ---- Coalesced loads: 2 float4 per channel (lane stride 32B) ----
        float tv[8], wx[8], wy[8], wz[8], ax[8], ay[8], az[8];
        if (k + 7 < T) {
            float4 u, v;
            u = *reinterpret_cast<const float4*>(tt + k);
            v = *reinterpret_cast<const float4*>(tt + k + 4);
            tv[0]=u.x; tv[1]=u.y; tv[2]=u.z; tv[3]=u.w; tv[4]=v.x; tv[5]=v.y; tv[6]=v.z; tv[7]=v.w;
            u = *reinterpret_cast<const float4*>(w0 + k);
            v = *reinterpret_cast<const float4*>(w0 + k + 4);
            wx[0]=u.x; wx[1]=u.y; wx[2]=u.z; wx[3]=u.w; wx[4]=v.x; wx[5]=v.y; wx[6]=v.z; wx[7]=v.w;
            u = *reinterpret_cast<const float4*>(w1 + k);
            v = *reinterpret_cast<const float4*>(w1 + k + 4);
            wy[0]=u.x; wy[1]=u.y; wy[2]=u.z; wy[3]=u.w; wy[4]=v.x; wy[5]=v.y; wy[6]=v.z; wy[7]=v.w;
            u = *reinterpret_cast<const float4*>(w2 + k);
            v = *reinterpret_cast<const float4*>(w2 + k + 4);
            wz[0]=u.x; wz[1]=u.y; wz[2]=u.z; wz[3]=u.w; wz[4]=v.x; wz[5]=v.y; wz[6]=v.z; wz[7]=v.w;
            u = *reinterpret_cast<const float4*>(a0 + k);
            v = *reinterpret_cast<const float4*>(a0 + k + 4);
            ax[0]=u.x; ax[1]=u.y; ax[2]=u.z; ax[3]=u.w; ax[4]=v.x; ax[5]=v.y; ax[6]=v.z; ax[7]=v.w;
            u = *reinterpret_cast<const float4*>(a1 + k);
            v = *reinterpret_cast<const float4*>(a1 + k + 4);
            ay[0]=u.x; ay[1]=u.y; ay[2]=u.z; ay[3]=u.w; ay[4]=v.x; ay[5]=v.y; ay[6]=v.z; ay[7]=v.w;
            u = *reinterpret_cast<const float4*>(a2 + k);
            v = *reinterpret_cast<const float4*>(a2 + k + 4);
            az[0]=u.x; az[1]=u.y; az[2]=u.z; az[3]=u.w; az[4]=v.x; az[5]=v.y; az[6]=v.z; az[7]=v.w;
        } else {
            #pragma unroll
            for (int j = 0; j < 8; j++) {
                bool ok = (k + j) < T;
                tv[j] = ok ? tt[k + j] : 0.f;
                wx[j] = ok ? w0[k + j] : 0.f;
                wy[j] = ok ? w1[k + j] : 0.f;
                wz[j] = ok ? w2[k + j] : 0.f;
                ax[j] = ok ? a0[k + j] : 0.f;
                ay[j] = ok ? a1[k + j] : 0.f;
                az[j] = ok ? a2[k + j] : 0.f;
            }
        }

        // t[k+8]: next lane's tv[0]; lane 31 loads it (or 0 past end)
        float tnext = __shfl_down_sync(0xffffffffu, tv[0], 1);
        if (lane == 31) {
            int kn = rbase + 256;
            tnext = (kn < T) ? tt[kn] : 0.f;
        }

        float dts[8];
        #pragma unroll
        for (int j = 0; j < 7; j++) dts[j] = tv[j + 1] - tv[j];
        dts[7] = tnext - tv[7];
        #pragma unroll
        for (int j = 0; j < 8; j++) {
            if (k + j >= nsteps) dts[j] = 0.f;   // identity step
        }

        // ---- Integrate 8 steps from identity ----
        float Q[9] = {1.f,0.f,0.f, 0.f,1.f,0.f, 0.f,0.f,1.f};
        float p[3] = {0.f,0.f,0.f};
        float r[3] = {0.f,0.f,0.f};
        float tau  = 0.f;

        #pragma unroll
        for (int j = 0; j < 8; j++) {
            float dt = dts[j];
            float aX = ax[j], aY = ay[j], aZ = az[j];
            float ca0 = Q[0]*aX + Q[1]*aY + Q[2]*aZ;
            float ca1 = Q[3]*aX + Q[4]*aY + Q[5]*aZ;
            float ca2 = Q[6]*aX + Q[7]*aY + Q[8]*aZ;
            float hdt2 = 0.5f * dt * dt;
            r[0] += p[0]*dt + ca0*hdt2;
            r[1] += p[1]*dt + ca1*hdt2;
            r[2] += p[2]*dt + ca2*hdt2;
            p[0] += ca0*dt;
            p[1] += ca1*dt;
            p[2] += ca2*dt;
            tau  += dt;

            float px = wx[j]*dt, py = wy[j]*dt, pz = wz[j]*dt;
            float t2 = px*px + py*py + pz*pz;
            float A, Bc;
            so3_AB(t2, A, Bc);
            float Bxy = Bc*px*py, Bxz = Bc*px*pz, Byz = Bc*py*pz;
            float R00 = 1.0f + Bc*(px*px - t2);
            float R11 = 1.0f + Bc*(py*py - t2);
            float R22 = 1.0f + Bc*(pz*pz - t2);
            float R01 = Bxy - A*pz;
            float R10 = Bxy + A*pz;
            float R02 = Bxz + A*py;
            float R20 = Bxz - A*py;
            float R12 = Byz - A*px;
            float R21 = Byz + A*px;

            float n0 = Q[0]*R00 + Q[1]*R10 + Q[2]*R20;
            float n1 = Q[0]*R01 + Q[1]*R11 + Q[2]*R21;
            float n2 = Q[0]*R02 + Q[1]*R12 + Q[2]*R22;
            float n3 = Q[3]*R00 + Q[4]*R10 + Q[5]*R20;
            float n4 = Q[3]*R01 + Q[4]*R11 + Q[5]*R21;
            float n5 = Q[3]*R02 + Q[4]*R12 + Q[5]*R22;
            float n6 = Q[6]*R00 + Q[7]*R10 + Q[8]*R20;
            float n7 = Q[6]*R01 + Q[7]*R11 + Q[8]*R21;
            float n8 = Q[6]*R02 + Q[7]*R12 + Q[8]*R22;
            Q[0]=n0; Q[1]=n1; Q[2]=n2;
            Q[3]=n3; Q[4]=n4; Q[5]=n5;
            Q[6]=n6; Q[7]=n7; Q[8]=n8;
        }

        // ---- Warp tree reduce (ordered, valid on lane 0) ----
        #pragma unroll
        for (int off = 1; off < 32; off <<= 1) {
            float Q2[9], p2[3], r2[3], tau2;
            #pragma unroll
            for (int i = 0; i < 9; i++) Q2[i] = __shfl_down_sync(0xffffffffu, Q[i], off);
            #pragma unroll
            for (int i = 0; i < 3; i++) p2[i] = __shfl_down_sync(0xffffffffu, p[i], off);
            #pragma unroll
            for (int i = 0; i < 3; i++) r2[i] = __shfl_down_sync(0xffffffffu, r[i], off);
            tau2 = __shfl_down_sync(0xffffffffu, tau, off);

            float nQ[9];
            #pragma unroll
            for (int i = 0; i < 3; i++) {
                #pragma unroll
                for (int jj = 0; jj < 3; jj++)
                    nQ[3*i+jj] = Q[3*i+0]*Q2[0+jj] + Q[3*i+1]*Q2[3+jj] + Q[3*i+2]*Q2[6+jj];
            }
            float np[3], nr[3];
            #pragma unroll
            for (int i = 0; i < 3; i++) {
                float Qp = Q[3*i+0]*p2[0] + Q[3*i+1]*p2[1] + Q[3*i+2]*p2[2];
                float Qr = Q[3*i+0]*r2[0] + Q[3*i+1]*r2[1] + Q[3*i+2]*r2[2];
                np[i] = p[i] + Qp;
                nr[i] = r[i] + tau2 * p[i] + Qr;
            }
            #pragma unroll
            for (int i = 0; i < 9; i++) Q[i] = nQ[i];
            #pragma unroll
            for (int i = 0; i < 3; i++) { p[i] = np[i]; r[i] = nr[i]; }
            tau += tau2;
        }

        // ---- Fold round into running total (lane 0's values are the real ones;
        //      other lanes compute garbage harmlessly) ----
        if (rr == 0) {
            #pragma unroll
            for (int i = 0; i < 9; i++) TQ[i] = Q[i];
            #pragma unroll
            for (int i = 0; i < 3; i++) { Tp[i] = p[i]; Tr[i] = r[i]; }
            Ttau = tau;
        } else {
            float nQ[9];
            #pragma unroll
            for (int i = 0; i < 3; i++) {
                #pragma unroll
                for (int jj = 0; jj < 3; jj++)
                    nQ[3*i+jj] = TQ[3*i+0]*Q[0+jj] + TQ[3*i+1]*Q[3+jj] + TQ[3*i+2]*Q[6+jj];
            }
            float np[3], nr[3];
            #pragma unroll
            for (int i = 0; i < 3; i++) {
                float Qp = TQ[3*i+0]*p[0] + TQ[3*i+1]*p[1] + TQ[3*i+2]*p[2];
                float Qr = TQ[3*i+0]*r[0] + TQ[3*i+1]*r[1] + TQ[3*i+2]*r[2];
                np[i] = Tp[i] + Qp;
                nr[i] = Tr[i] + tau * Tp[i] + Qr;
            }
            #pragma unroll
            for (int i = 0; i < 9; i++) TQ[i] = nQ[i];
            #pragma unroll
            for (int i = 0; i < 3; i++) { Tp[i] = np[i]; Tr[i] = nr[i]; }
            Ttau += tau;
        }
    }

    if (lane == 0) {
        float* o = out + (size_t)b * 15;
        #pragma unroll
        for (int i = 0; i < 9; i++) o[i] = TQ[i];
        o[9]  = Tp[0]; o[10] = Tp[1]; o[11] = Tp[2];
        o[12] = Tr[0]; o[13] = Tr[1]; o[14] = Tr[2];
    }
}

extern "C" void kernel_launch(void* const* d_in, const int* in_sizes, int n_in,
                              void* d_out, int out_size) {
    const float* x = (const float*)d_in[0];
    float* out = (float*)d_out;

    int B = out_size / 15;
    int T = in_sizes[0] / (7 * B);

    const int THREADS = 128;                 // 4 warps = 4 batches per block
    int blocks = (B * 32 + THREADS - 1) / THREADS;
    rmi_kernel<<<blocks, THREADS>>>(x, out, B, T);
}

// round 3
// speedup vs baseline: 1.3083x; 1.0631x over previous
#include <cuda_runtime.h>

// IMU preintegration (RmiModel). Associative segment composition:
//   segment = (Q, p, r, tau);
//   compose: Q=Q1Q2, p=p1+Q1 p2, r=r1+tau2 p1+Q1 r2, tau=tau1+tau2.
// 4 warps per batch (block = 128 thr = 1 batch). Warp w covers the contiguous
// step range [w*chunk, (w+1)*chunk). Within a warp, each lane integrates 8
// contiguous steps per 256-step round (lane stride 32B -> coalesced float4
// loads, 4 L1 lines per LDG), then a 5-stage shfl_down tree composes the 32
// lane segments (valid on lane 0). Warp totals are composed via smem by warp 0.

__device__ __forceinline__ void so3_AB(float t2, float& A, float& Bc) {
    if (t2 > 0.25f) {               // exact fallback (never taken on this data)
        float th = sqrtf(t2);
        A  = sinf(th) / th;
        Bc = (1.0f - cosf(th)) / t2;
    } else {                        // Taylor, |err| < 1e-8 for t2 <= 0.25
        A  = 1.0f + t2 * (-1.0f/6.0f  + t2 * (1.0f/120.0f + t2 * (-1.0f/5040.0f)));
        Bc = 0.5f + t2 * (-1.0f/24.0f + t2 * (1.0f/720.0f + t2 * (-1.0f/40320.0f)));
    }
}

// T1 <- T1 ∘ T2  (T1 is the earlier segment)
__device__ __forceinline__ void compose(float Q1[9], float p1[3], float r1[3], float& tau1,
                                        const float Q2[9], const float p2[3],
                                        const float r2[3], float tau2) {
    float nQ[9];
    #pragma unroll
    for (int i = 0; i < 3; i++) {
        #pragma unroll
        for (int j = 0; j < 3; j++)
            nQ[3*i+j] = Q1[3*i+0]*Q2[0+j] + Q1[3*i+1]*Q2[3+j] + Q1[3*i+2]*Q2[6+j];
    }
    float np[3], nr[3];
    #pragma unroll
    for (int i = 0; i < 3; i++) {
        float Qp = Q1[3*i+0]*p2[0] + Q1[3*i+1]*p2[1] + Q1[3*i+2]*p2[2];
        float Qr = Q1[3*i+0]*r2[0] + Q1[3*i+1]*r2[1] + Q1[3*i+2]*r2[2];
        np[i] = p1[i] + Qp;
        nr[i] = r1[i] + tau2 * p1[i] + Qr;
    }
    #pragma unroll
    for (int i = 0; i < 9; i++) Q1[i] = nQ[i];
    #pragma unroll
    for (int i = 0; i < 3; i++) { p1[i] = np[i]; r1[i] = nr[i]; }
    tau1 += tau2;
}

// One integration step applied to local segment state (Q,p,r,tau)
__device__ __forceinline__ void step(float Q[9], float p[3], float r[3], float& tau,
                                     float dt, float aX, float aY, float aZ,
                                     float wX, float wY, float wZ) {
    float ca0 = Q[0]*aX + Q[1]*aY + Q[2]*aZ;
    float ca1 = Q[3]*aX + Q[4]*aY + Q[5]*aZ;
    float ca2 = Q[6]*aX + Q[7]*aY + Q[8]*aZ;
    float hdt2 = 0.5f * dt * dt;
    r[0] += p[0]*dt + ca0*hdt2;
    r[1] += p[1]*dt + ca1*hdt2;
    r[2] += p[2]*dt + ca2*hdt2;
    p[0] += ca0*dt;
    p[1] += ca1*dt;
    p[2] += ca2*dt;
    tau  += dt;

    float px = wX*dt, py = wY*dt, pz = wZ*dt;
    float t2 = px*px + py*py + pz*pz;
    float A, Bc;
    so3_AB(t2, A, Bc);
    float Bxy = Bc*px*py, Bxz = Bc*px*pz, Byz = Bc*py*pz;
    float R00 = 1.0f + Bc*(px*px - t2);
    float R11 = 1.0f + Bc*(py*py - t2);
    float R22 = 1.0f + Bc*(pz*pz - t2);
    float R01 = Bxy - A*pz;
    float R10 = Bxy + A*pz;
    float R02 = Bxz + A*py;
    float R20 = Bxz - A*py;
    float R12 = Byz - A*px;
    float R21 = Byz + A*px;

    float n0 = Q[0]*R00 + Q[1]*R10 + Q[2]*R20;
    float n1 = Q[0]*R01 + Q[1]*R11 + Q[2]*R21;
    float n2 = Q[0]*R02 + Q[1]*R12 + Q[2]*R22;
    float n3 = Q[3]*R00 + Q[4]*R10 + Q[5]*R20;
    float n4 = Q[3]*R01 + Q[4]*R11 + Q[5]*R21;
    float n5 = Q[3]*R02 + Q[4]*R12 + Q[5]*R22;
    float n6 = Q[6]*R00 + Q[7]*R10 + Q[8]*R20;
    float n7 = Q[6]*R01 + Q[7]*R11 + Q[8]*R21;
    float n8 = Q[6]*R02 + Q[7]*R12 + Q[8]*R22;
    Q[0]=n0; Q[1]=n1; Q[2]=n2;
    Q[3]=n3; Q[4]=n4; Q[5]=n5;
    Q[6]=n6; Q[7]=n7; Q[8]=n8;
}

__global__ __launch_bounds__(128, 5)
void rmi_kernel(const float* __restrict__ x, float* __restrict__ out,
                int B, int T, int chunk)
{
    const int b    = blockIdx.x;
    const int warp = threadIdx.x >> 5;
    const int lane = threadIdx.x & 31;
    const int nsteps = T - 1;

    const size_t base = (size_t)b * 7 * (size_t)T;
    const float* tt = x + base;
    const float* w0 = x + base + 1 * (size_t)T;
    const float* w1 = x + base + 2 * (size_t)T;
    const float* w2 = x + base + 3 * (size_t)T;
    const float* a0 = x + base + 4 * (size_t)T;
    const float* a1 = x + base + 5 * (size_t)T;
    const float* a2 = x + base + 6 * (size_t)T;

    // Per-warp running total (valid on lane 0)
    float TQ[9] = {1.f,0.f,0.f, 0.f,1.f,0.f, 0.f,0.f,1.f};
    float Tp[3] = {0.f,0.f,0.f};
    float Tr[3] = {0.f,0.f,0.f};
    float Ttau  = 0.f;

    const int rounds = chunk >> 8;   // 256 steps per round

    for (int rr = 0; rr < rounds; rr++) {
        const int k = warp * chunk + rr * 256 + lane * 8;

        // ---- time channel & dts ----
        float tv[8];
        if (k + 7 < T) {
            float4 u = *reinterpret_cast<const float4*>(tt + k);
            float4 v = *reinterpret_cast<const float4*>(tt + k + 4);
            tv[0]=u.x; tv[1]=u.y; tv[2]=u.z; tv[3]=u.w;
            tv[4]=v.x; tv[5]=v.y; tv[6]=v.z; tv[7]=v.w;
        } else {
            #pragma unroll
            for (int j = 0; j < 8; j++) tv[j] = (k + j < T) ? tt[k + j] : 0.f;
        }
        float tnext = __shfl_down_sync(0xffffffffu, tv[0], 1);
        if (lane == 31) {
            int kn = k + 8;
            tnext = (kn < T) ? tt[kn] : 0.f;
        }
        float dts[8];
        #pragma unroll
        for (int j = 0; j < 7; j++) dts[j] = tv[j + 1] - tv[j];
        dts[7] = tnext - tv[7];
        #pragma unroll
        for (int j = 0; j < 8; j++)
            if (k + j >= nsteps) dts[j] = 0.f;   // identity step

        // ---- integrate 8 steps from identity, in two 4-step phases ----
        float Q[9] = {1.f,0.f,0.f, 0.f,1.f,0.f, 0.f,0.f,1.f};
        float p[3] = {0.f,0.f,0.f};
        float r[3] = {0.f,0.f,0.f};
        float tau  = 0.f;

        #pragma unroll
        for (int ph = 0; ph < 2; ph++) {
            const int kk = k + ph * 4;
            float4 vwx, vwy, vwz, vax, vay, vaz;
            if (kk + 3 < T) {
                vwx = *reinterpret_cast<const float4*>(w0 + kk);
                vwy = *reinterpret_cast<const float4*>(w1 + kk);
                vwz = *reinterpret_cast<const float4*>(w2 + kk);
                vax = *reinterpret_cast<const float4*>(a0 + kk);
                vay = *reinterpret_cast<const float4*>(a1 + kk);
                vaz = *reinterpret_cast<const float4*>(a2 + kk);
            } else {
                float tmp[6][4];
                #pragma unroll
                for (int j = 0; j < 4; j++) {
                    bool ok = (kk + j) < T;
                    tmp[0][j] = ok ? w0[kk + j] : 0.f;
                    tmp[1][j] = ok ? w1[kk + j] : 0.f;
                    tmp[2][j] = ok ? w2[kk + j] : 0.f;
                    tmp[3][j] = ok ? a0[kk + j] : 0.f;
                    tmp[4][j] = ok ? a1[kk + j] : 0.f;
                    tmp[5][j] = ok ? a2[kk + j] : 0.f;
                }
                vwx = make_float4(tmp[0][0], tmp[0][1], tmp[0][2], tmp[0][3]);
                vwy = make_float4(tmp[1][0], tmp[1][1], tmp[1][2], tmp[1][3]);
                vwz = make_float4(tmp[2][0], tmp[2][1], tmp[2][2], tmp[2][3]);
                vax = make_float4(tmp[3][0], tmp[3][1], tmp[3][2], tmp[3][3]);
                vay = make_float4(tmp[4][0], tmp[4][1], tmp[4][2], tmp[4][3]);
                vaz = make_float4(tmp[5][0], tmp[5][1], tmp[5][2], tmp[5][3]);
            }
            step(Q, p, r, tau, dts[ph*4+0], vax.x, vay.x, vaz.x, vwx.x, vwy.x, vwz.x);
            step(Q, p, r, tau, dts[ph*4+1], vax.y, vay.y, vaz.y, vwx.y, vwy.y, vwz.y);
            step(Q, p, r, tau, dts[ph*4+2], vax.z, vay.z, vaz.z, vwx.z, vwy.z, vwz.z);
            step(Q, p, r, tau, dts[ph*4+3], vax.w, vay.w, vaz.w, vwx.w, vwy.w, vwz.w);
        }

        // ---- warp tree reduce (ordered, valid on lane 0) ----
        #pragma unroll
        for (int off = 1; off < 32; off <<= 1) {
            float Q2[9], p2[3], r2[3], tau2;
            #pragma unroll
            for (int i = 0; i < 9; i++) Q2[i] = __shfl_down_sync(0xffffffffu, Q[i], off);
            #pragma unroll
            for (int i = 0; i < 3; i++) p2[i] = __shfl_down_sync(0xffffffffu, p[i], off);
            #pragma unroll
            for (int i = 0; i < 3; i++) r2[i] = __shfl_down_sync(0xffffffffu, r[i], off);
            tau2 = __shfl_down_sync(0xffffffffu, tau, off);
            compose(Q, p, r, tau, Q2, p2, r2, tau2);
        }

        // ---- fold into warp total (identity-init makes rr==0 exact copy) ----
        compose(TQ, Tp, Tr, Ttau, Q, p, r, tau);
    }

    // ---- cross-warp combine via smem ----
    __shared__ float seg[4][16];
    if (lane == 0) {
        #pragma unroll
        for (int i = 0; i < 9; i++) seg[warp][i] = TQ[i];
        seg[warp][9]  = Tp[0]; seg[warp][10] = Tp[1]; seg[warp][11] = Tp[2];
        seg[warp][12] = Tr[0]; seg[warp][13] = Tr[1]; seg[warp][14] = Tr[2];
        seg[warp][15] = Ttau;
    }
    __syncthreads();

    if (warp == 0) {
        float FQ[9], Fp[3], Fr[3], Ftau;
        #pragma unroll
        for (int i = 0; i < 9; i++) FQ[i] = seg[0][i];
        Fp[0]=seg[0][9];  Fp[1]=seg[0][10]; Fp[2]=seg[0][11];
        Fr[0]=seg[0][12]; Fr[1]=seg[0][13]; Fr[2]=seg[0][14];
        Ftau = seg[0][15];
        #pragma unroll
        for (int wsg = 1; wsg < 4; wsg++) {
            float Q2[9], p2[3], r2[3], tau2;
            #pragma unroll
            for (int i = 0; i < 9; i++) Q2[i] = seg[wsg][i];
            p2[0]=seg[wsg][9];  p2[1]=seg[wsg][10]; p2[2]=seg[wsg][11];
            r2[0]=seg[wsg][12]; r2[1]=seg[wsg][13]; r2[2]=seg[wsg][14];
            tau2 = seg[wsg][15];
            compose(FQ, Fp, Fr, Ftau, Q2, p2, r2, tau2);
        }
        if (lane == 0) {
            float* o = out + (size_t)b * 15;
            #pragma unroll
            for (int i = 0; i < 9; i++) o[i] = FQ[i];
            o[9]  = Fp[0]; o[10] = Fp[1]; o[11] = Fp[2];
            o[12] = Fr[0]; o[13] = Fr[1]; o[14] = Fr[2];
        }
    }
}

extern "C" void kernel_launch(void* const* d_in, const int* in_sizes, int n_in,
                              void* d_out, int out_size) {
    const float* x = (const float*)d_in[0];
    float* out = (float*)d_out;

    int B = out_size / 15;
    int T = in_sizes[0] / (7 * B);
    int nsteps = T - 1;

    // per-warp contiguous chunk, multiple of 256, 4 warps cover all steps
    int chunk = ((nsteps + 1023) / 1024) * 256;

    rmi_kernel<<<B, 128>>>(x, out, B, T, chunk);
}

// round 4
// speedup vs baseline: 1.4667x; 1.1210x over previous
#include <cuda_runtime.h>

// IMU preintegration (RmiModel). Associative segment composition:
//   segment = (Q, p, r, tau);
//   compose: Q=Q1Q2, p=p1+Q1 p2, r=r1+tau2 p1+Q1 r2, tau=tau1+tau2.
// 4 warps per batch (block = 128 thr = 1 batch). Warp w covers steps
// [w*chunk, (w+1)*chunk). Each lane integrates 8 contiguous steps per 256-step
// round (coalesced float4 loads), then a 5-stage shfl_down tree composes the
// 32 lane segments (valid on lane 0). Warp totals composed via smem by warp 0.
// Round 0 writes the warp total directly so the total is not live during
// integration (register pressure -> occupancy).

__device__ __forceinline__ void so3_R(float px, float py, float pz, float R[9]) {
    float t2 = px*px + py*py + pz*pz;
    float A, Bc;
    if (t2 > 0.25f) {                 // fast intrinsic fallback (not taken on this data)
        float th = __fsqrt_rn(t2);
        float s, c;
        __sincosf(th, &s, &c);
        A  = s / th;
        Bc = (1.0f - c) / t2;
    } else {                          // Taylor, |err| < 1e-8 for t2 <= 0.25
        A  = 1.0f + t2 * (-1.0f/6.0f  + t2 * (1.0f/120.0f + t2 * (-1.0f/5040.0f)));
        Bc = 0.5f + t2 * (-1.0f/24.0f + t2 * (1.0f/720.0f + t2 * (-1.0f/40320.0f)));
    }
    float Bxy = Bc*px*py, Bxz = Bc*px*pz, Byz = Bc*py*pz;
    R[0] = 1.0f + Bc*(px*px - t2);
    R[4] = 1.0f + Bc*(py*py - t2);
    R[8] = 1.0f + Bc*(pz*pz - t2);
    R[1] = Bxy - A*pz;
    R[3] = Bxy + A*pz;
    R[2] = Bxz + A*py;
    R[6] = Bxz - A*py;
    R[5] = Byz - A*px;
    R[7] = Byz + A*px;
}

// General step: state (Q,p,r,tau) <- state ∘ step(dt, a, w)
__device__ __forceinline__ void step(float Q[9], float p[3], float r[3], float& tau,
                                     float dt, float aX, float aY, float aZ,
                                     float wX, float wY, float wZ) {
    float ca0 = Q[0]*aX + Q[1]*aY + Q[2]*aZ;
    float ca1 = Q[3]*aX + Q[4]*aY + Q[5]*aZ;
    float ca2 = Q[6]*aX + Q[7]*aY + Q[8]*aZ;
    float hdt2 = 0.5f * dt * dt;
    r[0] += p[0]*dt + ca0*hdt2;
    r[1] += p[1]*dt + ca1*hdt2;
    r[2] += p[2]*dt + ca2*hdt2;
    p[0] += ca0*dt;
    p[1] += ca1*dt;
    p[2] += ca2*dt;
    tau  += dt;

    float R[9];
    so3_R(wX*dt, wY*dt, wZ*dt, R);

    float n0 = Q[0]*R[0] + Q[1]*R[3] + Q[2]*R[6];
    float n1 = Q[0]*R[1] + Q[1]*R[4] + Q[2]*R[7];
    float n2 = Q[0]*R[2] + Q[1]*R[5] + Q[2]*R[8];
    float n3 = Q[3]*R[0] + Q[4]*R[3] + Q[5]*R[6];
    float n4 = Q[3]*R[1] + Q[4]*R[4] + Q[5]*R[7];
    float n5 = Q[3]*R[2] + Q[4]*R[5] + Q[5]*R[8];
    float n6 = Q[6]*R[0] + Q[7]*R[3] + Q[8]*R[6];
    float n7 = Q[6]*R[1] + Q[7]*R[4] + Q[8]*R[7];
    float n8 = Q[6]*R[2] + Q[7]*R[5] + Q[8]*R[8];
    Q[0]=n0; Q[1]=n1; Q[2]=n2;
    Q[3]=n3; Q[4]=n4; Q[5]=n5;
    Q[6]=n6; Q[7]=n7; Q[8]=n8;
}

// T1 <- T1 ∘ T2
__device__ __forceinline__ void compose(float Q1[9], float p1[3], float r1[3], float& tau1,
                                        const float Q2[9], const float p2[3],
                                        const float r2[3], float tau2) {
    float nQ[9];
    #pragma unroll
    for (int i = 0; i < 3; i++) {
        #pragma unroll
        for (int j = 0; j < 3; j++)
            nQ[3*i+j] = Q1[3*i+0]*Q2[0+j] + Q1[3*i+1]*Q2[3+j] + Q1[3*i+2]*Q2[6+j];
    }
    float np[3], nr[3];
    #pragma unroll
    for (int i = 0; i < 3; i++) {
        float Qp = Q1[3*i+0]*p2[0] + Q1[3*i+1]*p2[1] + Q1[3*i+2]*p2[2];
        float Qr = Q1[3*i+0]*r2[0] + Q1[3*i+1]*r2[1] + Q1[3*i+2]*r2[2];
        np[i] = p1[i] + Qp;
        nr[i] = r1[i] + tau2 * p1[i] + Qr;
    }
    #pragma unroll
    for (int i = 0; i < 9; i++) Q1[i] = nQ[i];
    #pragma unroll
    for (int i = 0; i < 3; i++) { p1[i] = np[i]; r1[i] = nr[i]; }
    tau1 += tau2;
}

// One 256-step round for this warp: integrate 8 steps/lane + tree reduce.
// Result (valid on lane 0) in (Q,p,r,tau).
__device__ __forceinline__ void warp_round(const float* __restrict__ tt,
                                           const float* __restrict__ w0,
                                           const float* __restrict__ w1,
                                           const float* __restrict__ w2,
                                           const float* __restrict__ a0,
                                           const float* __restrict__ a1,
                                           const float* __restrict__ a2,
                                           int k, int T, int nsteps, int lane,
                                           float Q[9], float p[3], float r[3], float& tau) {
    // ---- time channel & dts ----
    float tv[8];
    if (k + 7 < T) {
        float4 u = *reinterpret_cast<const float4*>(tt + k);
        float4 v = *reinterpret_cast<const float4*>(tt + k + 4);
        tv[0]=u.x; tv[1]=u.y; tv[2]=u.z; tv[3]=u.w;
        tv[4]=v.x; tv[5]=v.y; tv[6]=v.z; tv[7]=v.w;
    } else {
        #pragma unroll
        for (int j = 0; j < 8; j++) tv[j] = (k + j < T) ? tt[k + j] : 0.f;
    }
    float tnext = __shfl_down_sync(0xffffffffu, tv[0], 1);
    if (lane == 31) {
        int kn = k + 8;
        tnext = (kn < T) ? tt[kn] : 0.f;
    }
    float dts[8];
    #pragma unroll
    for (int j = 0; j < 7; j++) dts[j] = tv[j + 1] - tv[j];
    dts[7] = tnext - tv[7];
    #pragma unroll
    for (int j = 0; j < 8; j++)
        if (k + j >= nsteps) dts[j] = 0.f;     // identity step

    // ---- integrate: phase 0 (steps 0-3, step 0 specialized from identity) ----
    {
        float4 vwx, vwy, vwz, vax, vay, vaz;
        if (k + 3 < T) {
            vwx = *reinterpret_cast<const float4*>(w0 + k);
            vwy = *reinterpret_cast<const float4*>(w1 + k);
            vwz = *reinterpret_cast<const float4*>(w2 + k);
            vax = *reinterpret_cast<const float4*>(a0 + k);
            vay = *reinterpret_cast<const float4*>(a1 + k);
            vaz = *reinterpret_cast<const float4*>(a2 + k);
        } else {
            float tmp[6][4];
            #pragma unroll
            for (int j = 0; j < 4; j++) {
                bool ok = (k + j) < T;
                tmp[0][j] = ok ? w0[k + j] : 0.f;
                tmp[1][j] = ok ? w1[k + j] : 0.f;
                tmp[2][j] = ok ? w2[k + j] : 0.f;
                tmp[3][j] = ok ? a0[k + j] : 0.f;
                tmp[4][j] = ok ? a1[k + j] : 0.f;
                tmp[5][j] = ok ? a2[k + j] : 0.f;
            }
            vwx = make_float4(tmp[0][0], tmp[0][1], tmp[0][2], tmp[0][3]);
            vwy = make_float4(tmp[1][0], tmp[1][1], tmp[1][2], tmp[1][3]);
            vwz = make_float4(tmp[2][0], tmp[2][1], tmp[2][2], tmp[2][3]);
            vax = make_float4(tmp[3][0], tmp[3][1], tmp[3][2], tmp[3][3]);
            vay = make_float4(tmp[4][0], tmp[4][1], tmp[4][2], tmp[4][3]);
            vaz = make_float4(tmp[5][0], tmp[5][1], tmp[5][2], tmp[5][3]);
        }
        // step 0 from identity: ca = a, p was 0, r was 0, Q = R
        {
            float dt = dts[0];
            float hdt2 = 0.5f * dt * dt;
            r[0] = vax.x * hdt2;  r[1] = vay.x * hdt2;  r[2] = vaz.x * hdt2;
            p[0] = vax.x * dt;    p[1] = vay.x * dt;    p[2] = vaz.x * dt;
            tau  = dt;
            so3_R(vwx.x*dt, vwy.x*dt, vwz.x*dt, Q);
        }
        step(Q, p, r, tau, dts[1], vax.y, vay.y, vaz.y, vwx.y, vwy.y, vwz.y);
        step(Q, p, r, tau, dts[2], vax.z, vay.z, vaz.z, vwx.z, vwy.z, vwz.z);
        step(Q, p, r, tau, dts[3], vax.w, vay.w, vaz.w, vwx.w, vwy.w, vwz.w);
    }
    // ---- phase 1 (steps 4-7) ----
    {
        const int kk = k + 4;
        float4 vwx, vwy, vwz, vax, vay, vaz;
        if (kk + 3 < T) {
            vwx = *reinterpret_cast<const float4*>(w0 + kk);
            vwy = *reinterpret_cast<const float4*>(w1 + kk);
            vwz = *reinterpret_cast<const float4*>(w2 + kk);
            vax = *reinterpret_cast<const float4*>(a0 + kk);
            vay = *reinterpret_cast<const float4*>(a1 + kk);
            vaz = *reinterpret_cast<const float4*>(a2 + kk);
        } else {
            float tmp[6][4];
            #pragma unroll
            for (int j = 0; j < 4; j++) {
                bool ok = (kk + j) < T;
                tmp[0][j] = ok ? w0[kk + j] : 0.f;
                tmp[1][j] = ok ? w1[kk + j] : 0.f;
                tmp[2][j] = ok ? w2[kk + j] : 0.f;
                tmp[3][j] = ok ? a0[kk + j] : 0.f;
                tmp[4][j] = ok ? a1[kk + j] : 0.f;
                tmp[5][j] = ok ? a2[kk + j] : 0.f;
            }
            vwx = make_float4(tmp[0][0], tmp[0][1], tmp[0][2], tmp[0][3]);
            vwy = make_float4(tmp[1][0], tmp[1][1], tmp[1][2], tmp[1][3]);
            vwz = make_float4(tmp[2][0], tmp[2][1], tmp[2][2], tmp[2][3]);
            vax = make_float4(tmp[3][0], tmp[3][1], tmp[3][2], tmp[3][3]);
            vay = make_float4(tmp[4][0], tmp[4][1], tmp[4][2], tmp[4][3]);
            vaz = make_float4(tmp[5][0], tmp[5][1], tmp[5][2], tmp[5][3]);
        }
        step(Q, p, r, tau, dts[4], vax.x, vay.x, vaz.x, vwx.x, vwy.x, vwz.x);
        step(Q, p, r, tau, dts[5], vax.y, vay.y, vaz.y, vwx.y, vwy.y, vwz.y);
        step(Q, p, r, tau, dts[6], vax.z, vay.z, vaz.z, vwx.z, vwy.z, vwz.z);
        step(Q, p, r, tau, dts[7], vax.w, vay.w, vaz.w, vwx.w, vwy.w, vwz.w);
    }

    // ---- warp tree reduce (ordered, valid on lane 0) ----
    #pragma unroll
    for (int off = 1; off < 32; off <<= 1) {
        float Q2[9], p2[3], r2[3], tau2;
        #pragma unroll
        for (int i = 0; i < 9; i++) Q2[i] = __shfl_down_sync(0xffffffffu, Q[i], off);
        #pragma unroll
        for (int i = 0; i < 3; i++) p2[i] = __shfl_down_sync(0xffffffffu, p[i], off);
        #pragma unroll
        for (int i = 0; i < 3; i++) r2[i] = __shfl_down_sync(0xffffffffu, r[i], off);
        tau2 = __shfl_down_sync(0xffffffffu, tau, off);
        compose(Q, p, r, tau, Q2, p2, r2, tau2);
    }
}

__global__ __launch_bounds__(128, 7)
void rmi_kernel(const float* __restrict__ x, float* __restrict__ out,
                int T, int chunk)
{
    const int b    = blockIdx.x;
    const int warp = threadIdx.x >> 5;
    const int lane = threadIdx.x & 31;
    const int nsteps = T - 1;

    const size_t base = (size_t)b * 7 * (size_t)T;
    const float* tt = x + base;
    const float* w0 = tt + T;
    const float* w1 = w0 + T;
    const float* w2 = w1 + T;
    const float* a0 = w2 + T;
    const float* a1 = a0 + T;
    const float* a2 = a1 + T;

    const int rounds = chunk >> 8;   // 256 steps per round

    // Round 0 -> warp total directly (TQ not live during integration)
    float TQ[9], Tp[3], Tr[3], Ttau;
    warp_round(tt, w0, w1, w2, a0, a1, a2,
               warp * chunk + lane * 8, T, nsteps, lane, TQ, Tp, Tr, Ttau);

    for (int rr = 1; rr < rounds; rr++) {
        float Q[9], p[3], r[3], tau;
        warp_round(tt, w0, w1, w2, a0, a1, a2,
                   warp * chunk + rr * 256 + lane * 8, T, nsteps, lane, Q, p, r, tau);
        compose(TQ, Tp, Tr, Ttau, Q, p, r, tau);
    }

    // ---- cross-warp combine via smem ----
    __shared__ float seg[4][16];
    if (lane == 0) {
        #pragma unroll
        for (int i = 0; i < 9; i++) seg[warp][i] = TQ[i];
        seg[warp][9]  = Tp[0]; seg[warp][10] = Tp[1]; seg[warp][11] = Tp[2];
        seg[warp][12] = Tr[0]; seg[warp][13] = Tr[1]; seg[warp][14] = Tr[2];
        seg[warp][15] = Ttau;
    }
    __syncthreads();

    if (warp == 0 && lane == 0) {
        float FQ[9], Fp[3], Fr[3], Ftau;
        #pragma unroll
        for (int i = 0; i < 9; i++) FQ[i] = seg[0][i];
        Fp[0]=seg[0][9];  Fp[1]=seg[0][10]; Fp[2]=seg[0][11];
        Fr[0]=seg[0][12]; Fr[1]=seg[0][13]; Fr[2]=seg[0][14];
        Ftau = seg[0][15];
        #pragma unroll
        for (int wsg = 1; wsg < 4; wsg++) {
            float Q2[9], p2[3], r2[3], tau2;
            #pragma unroll
            for (int i = 0; i < 9; i++) Q2[i] = seg[wsg][i];
            p2[0]=seg[wsg][9];  p2[1]=seg[wsg][10]; p2[2]=seg[wsg][11];
            r2[0]=seg[wsg][12]; r2[1]=seg[wsg][13]; r2[2]=seg[wsg][14];
            tau2 = seg[wsg][15];
            compose(FQ, Fp, Fr, Ftau, Q2, p2, r2, tau2);
        }
        float* o = out + (size_t)b * 15;
        #pragma unroll
        for (int i = 0; i < 9; i++) o[i] = FQ[i];
        o[9]  = Fp[0]; o[10] = Fp[1]; o[11] = Fp[2];
        o[12] = Fr[0]; o[13] = Fr[1]; o[14] = Fr[2];
    }
}

extern "C" void kernel_launch(void* const* d_in, const int* in_sizes, int n_in,
                              void* d_out, int out_size) {
    const float* x = (const float*)d_in[0];
    float* out = (float*)d_out;

    int B = out_size / 15;
    int T = in_sizes[0] / (7 * B);
    int nsteps = T - 1;

    // per-warp contiguous chunk, multiple of 256, 4 warps cover all steps
    int chunk = ((nsteps + 1023) / 1024) * 256;

    rmi_kernel<<<B, 128>>>(x, out, T, chunk);
}